// round 17
// baseline (speedup 1.0000x reference)
#include <cuda_runtime.h>
#include <cuda_bf16.h>
#include <mma.h>

using namespace nvcuda;

#define NB   4096
#define NB2  8192
#define NT   30
typedef __nv_bfloat16 bf16;

// ---------------- static device scratch ----------------
__device__ bf16  g_Xh [(size_t)NB2*NT*64],  g_Xl [(size_t)NB2*NT*64];
__device__ float g_XG1[(size_t)NB2*NT*2048];
__device__ bf16  g_S1h[(size_t)NB2*NT*512], g_S1l[(size_t)NB2*NT*512];
__device__ float g_XG2[(size_t)NB2*NT*512];
__device__ bf16  g_S2h[(size_t)NB2*NT*128], g_S2l[(size_t)NB2*NT*128];
__device__ float g_XG3[(size_t)NB2*NT*256];
__device__ bf16  g_S3h[(size_t)NB2*NT*64],  g_S3l[(size_t)NB2*NT*64];
__device__ bf16  g_Hah[NB2*512], g_Hal[NB2*512], g_Hbh[NB2*512], g_Hbl[NB2*512];
__device__ float g_Cc [NB2*512];
__device__ bf16  g_Dh [(size_t)NB*1920], g_Dl [(size_t)NB*1920];
__device__ bf16  g_F1h[(size_t)NB*960],  g_F1l[(size_t)NB*960];
__device__ float g_F2 [(size_t)NB*480];
// gate-interleaved split weights
__device__ bf16  g_W1ih_h[2048*64],  g_W1ih_l[2048*64];
__device__ bf16  g_W1hh_h[2048*512], g_W1hh_l[2048*512];
__device__ bf16  g_W2ih_h[512*512],  g_W2ih_l[512*512];
__device__ bf16  g_W2hh_h[512*128],  g_W2hh_l[512*128];
__device__ bf16  g_W3ih_h[256*128],  g_W3ih_l[256*128];
__device__ bf16  g_W3hh_h[256*64],   g_W3hh_l[256*64];
__device__ float g_b1p[2048], g_b2p[512], g_b3p[256];
__device__ bf16  g_Wf1h[(size_t)960*1920], g_Wf1l[(size_t)960*1920];
__device__ bf16  g_Wf2h[480*960],          g_Wf2l[480*960];

// ---------------- helpers ----------------
__device__ __forceinline__ float sigmf(float x) {
    return __fdividef(1.f, 1.f + __expf(-x));
}
__device__ __forceinline__ float tanh_f(float x) {
    float xc = fminf(fmaxf(x, -15.f), 15.f);
    float e  = __expf(2.f * xc);
    return __fdividef(e - 1.f, e + 1.f);
}
__device__ __forceinline__ void bsplit(float v, bf16& h, bf16& l) {
    h = __float2bfloat16(v);
    l = __float2bfloat16(v - __bfloat162float(h));
}

// ---------------- prep kernels ----------------
__global__ void pack_x(const float* __restrict__ x1, const float* __restrict__ x2,
                       bf16* __restrict__ Xh, bf16* __restrict__ Xl) {
    size_t i = (size_t)blockIdx.x * blockDim.x + threadIdx.x;
    if (i >= (size_t)NB2 * NT * 64) return;
    int    f  = (int)(i & 63);
    size_t bt = i >> 6;
    int    t  = (int)(bt % NT);
    size_t bb = bt / NT;
    int    br = (int)(bb >> 12);
    int    b  = (int)(bb & 4095);
    const float* x = br ? x2 : x1;
    float v = (f < 58) ? x[(size_t)b * (58 * 30) + f * 30 + t] : 0.f;
    bsplit(v, Xh[i], Xl[i]);
}

__global__ void perm_wih1_s(const float* __restrict__ W, bf16* __restrict__ Oh,
                            bf16* __restrict__ Ol) {
    int i = blockIdx.x * blockDim.x + threadIdx.x;
    if (i >= 2048 * 64) return;
    int f = i & 63, p = i >> 6;
    int u = p >> 2, g = p & 3;
    float v = (f < 58) ? W[(g * 512 + u) * 58 + f] : 0.f;
    bsplit(v, Oh[i], Ol[i]);
}

__global__ void perm_w_s(const float* __restrict__ W, bf16* __restrict__ Oh,
                         bf16* __restrict__ Ol, int H, int K) {
    int i = blockIdx.x * blockDim.x + threadIdx.x;
    if (i >= 4 * H * K) return;
    int k = i % K, p = i / K;
    int u = p >> 2, g = p & 3;
    bsplit(W[(size_t)(g * H + u) * K + k], Oh[i], Ol[i]);
}

__global__ void perm_b(const float* __restrict__ b, float* __restrict__ bp, int H) {
    int i = blockIdx.x * blockDim.x + threadIdx.x;
    if (i >= 4 * H) return;
    int u = i >> 2, g = i & 3;
    bp[i] = b[g * H + u];
}

__global__ void split_mat(const float* __restrict__ W, bf16* __restrict__ Oh,
                          bf16* __restrict__ Ol, size_t n) {
    size_t i = (size_t)blockIdx.x * blockDim.x + threadIdx.x;
    if (i >= n) return;
    bsplit(W[i], Oh[i], Ol[i]);
}

// ---------------- bf16x3 GEMM with pre-split operands ----------------
// C[M,N] = A[M,K]*B[N,K]^T (+bias)(+relu); out fp32 (Cf) or split pair (Ohg/Olg).
// Tile 128x64, 256 threads. M mult of 128, K mult of 32, N guarded.
#define SA_H 0
#define SA_L 10240
#define SB_H 20480
#define SB_L 25600

__global__ __launch_bounds__(256) void gemm_bs(
    const bf16* __restrict__ Ahg, const bf16* __restrict__ Alg,
    const bf16* __restrict__ Bhg, const bf16* __restrict__ Blg,
    const float* __restrict__ bias,
    float* __restrict__ Cf, bf16* __restrict__ Ohg, bf16* __restrict__ Olg,
    int M, int N, int K, int relu)
{
    __shared__ __align__(16) unsigned char sbuf[34816];
    bf16* sAh = (bf16*)(sbuf + SA_H);
    bf16* sAl = (bf16*)(sbuf + SA_L);
    bf16* sBh = (bf16*)(sbuf + SB_H);
    bf16* sBl = (bf16*)(sbuf + SB_L);
    float* Cs = (float*)sbuf;

    const int row0 = blockIdx.y * 128;
    const int col0 = blockIdx.x * 64;
    const int tid  = threadIdx.x;
    const int warp = tid >> 5;
    const int wm = (warp >> 1) * 32, wn = (warp & 1) * 32;

    wmma::fragment<wmma::accumulator, 16, 16, 16, float> acc[2][2];
#pragma unroll
    for (int i = 0; i < 2; i++)
#pragma unroll
        for (int j = 0; j < 2; j++) wmma::fill_fragment(acc[i][j], 0.f);

    for (int k0 = 0; k0 < K; k0 += 32) {
        __syncthreads();
#pragma unroll
        for (int tt = 0; tt < 2; tt++) {                  // A: 128 rows x 32 cols
            int idx = tid + tt * 256;
            int r = idx >> 2, c8 = (idx & 3) * 8;
            size_t go = (size_t)(row0 + r) * K + k0 + c8;
            *(uint4*)(sAh + r * 40 + c8) = *(const uint4*)(Ahg + go);
            *(uint4*)(sAl + r * 40 + c8) = *(const uint4*)(Alg + go);
        }
        {                                                  // B: 64 rows x 32 cols
            int r = tid >> 2, c8 = (tid & 3) * 8;
            int n = col0 + r;
            uint4 vh = make_uint4(0, 0, 0, 0), vl = make_uint4(0, 0, 0, 0);
            if (n < N) {
                size_t go = (size_t)n * K + k0 + c8;
                vh = *(const uint4*)(Bhg + go);
                vl = *(const uint4*)(Blg + go);
            }
            *(uint4*)(sBh + r * 40 + c8) = vh;
            *(uint4*)(sBl + r * 40 + c8) = vl;
        }
        __syncthreads();
#pragma unroll
        for (int kk = 0; kk < 32; kk += 16) {
            wmma::fragment<wmma::matrix_a, 16, 16, 16, bf16, wmma::row_major> ah[2], al[2];
            wmma::fragment<wmma::matrix_b, 16, 16, 16, bf16, wmma::col_major> bh[2], bl[2];
#pragma unroll
            for (int i = 0; i < 2; i++) {
                wmma::load_matrix_sync(ah[i], sAh + (wm + i * 16) * 40 + kk, 40);
                wmma::load_matrix_sync(al[i], sAl + (wm + i * 16) * 40 + kk, 40);
                wmma::load_matrix_sync(bh[i], sBh + (wn + i * 16) * 40 + kk, 40);
                wmma::load_matrix_sync(bl[i], sBl + (wn + i * 16) * 40 + kk, 40);
            }
#pragma unroll
            for (int i = 0; i < 2; i++)
#pragma unroll
                for (int j = 0; j < 2; j++) {
                    wmma::mma_sync(acc[i][j], ah[i], bh[j], acc[i][j]);
                    wmma::mma_sync(acc[i][j], ah[i], bl[j], acc[i][j]);
                    wmma::mma_sync(acc[i][j], al[i], bh[j], acc[i][j]);
                }
        }
    }
    __syncthreads();
#pragma unroll
    for (int i = 0; i < 2; i++)
#pragma unroll
        for (int j = 0; j < 2; j++)
            wmma::store_matrix_sync(Cs + (wm + i * 16) * 68 + wn + j * 16, acc[i][j], 68,
                                    wmma::mem_row_major);
    __syncthreads();

    for (int idx = tid; idx < 128 * 64; idx += 256) {
        int r = idx >> 6, c = idx & 63;
        int n = col0 + c;
        if (n < N) {
            float v = Cs[r * 68 + c];
            if (bias) v += bias[n];
            if (relu) v = fmaxf(v, 0.f);
            size_t o = (size_t)(row0 + r) * N + n;
            if (Cf) Cf[o] = v;
            else    bsplit(v, Ohg[o], Olg[o]);
        }
    }
}

// ---------------- fused recurrent step (pre-split H/W) ----------------
__global__ __launch_bounds__(256) void lstm_step(
    const bf16* __restrict__ Ahg, const bf16* __restrict__ Alg,
    const bf16* __restrict__ Whg, const bf16* __restrict__ Wlg,
    const float* __restrict__ XG, float* __restrict__ C,
    bf16* __restrict__ Hnh, bf16* __restrict__ Hnl,
    bf16* __restrict__ Sh,  bf16* __restrict__ Sl,
    int H, int t)
{
    const int K = H, N = 4 * H;
    __shared__ __align__(16) unsigned char sbuf[34816];
    bf16* sAh = (bf16*)(sbuf + SA_H);
    bf16* sAl = (bf16*)(sbuf + SA_L);
    bf16* sBh = (bf16*)(sbuf + SB_H);
    bf16* sBl = (bf16*)(sbuf + SB_L);
    float* Cs = (float*)sbuf;

    const int row0 = blockIdx.y * 128;
    const int col0 = blockIdx.x * 64;
    const int tid  = threadIdx.x;
    const int warp = tid >> 5;
    const int wm = (warp >> 1) * 32, wn = (warp & 1) * 32;

    wmma::fragment<wmma::accumulator, 16, 16, 16, float> acc[2][2];
#pragma unroll
    for (int i = 0; i < 2; i++)
#pragma unroll
        for (int j = 0; j < 2; j++) wmma::fill_fragment(acc[i][j], 0.f);

    for (int k0 = 0; k0 < K; k0 += 32) {
        __syncthreads();
#pragma unroll
        for (int tt = 0; tt < 2; tt++) {
            int idx = tid + tt * 256;
            int r = idx >> 2, c8 = (idx & 3) * 8;
            size_t go = (size_t)(row0 + r) * K + k0 + c8;
            *(uint4*)(sAh + r * 40 + c8) = *(const uint4*)(Ahg + go);
            *(uint4*)(sAl + r * 40 + c8) = *(const uint4*)(Alg + go);
        }
        {
            int r = tid >> 2, c8 = (tid & 3) * 8;
            size_t go = (size_t)(col0 + r) * K + k0 + c8;
            *(uint4*)(sBh + r * 40 + c8) = *(const uint4*)(Whg + go);
            *(uint4*)(sBl + r * 40 + c8) = *(const uint4*)(Wlg + go);
        }
        __syncthreads();
#pragma unroll
        for (int kk = 0; kk < 32; kk += 16) {
            wmma::fragment<wmma::matrix_a, 16, 16, 16, bf16, wmma::row_major> ah[2], al[2];
            wmma::fragment<wmma::matrix_b, 16, 16, 16, bf16, wmma::col_major> bh[2], bl[2];
#pragma unroll
            for (int i = 0; i < 2; i++) {
                wmma::load_matrix_sync(ah[i], sAh + (wm + i * 16) * 40 + kk, 40);
                wmma::load_matrix_sync(al[i], sAl + (wm + i * 16) * 40 + kk, 40);
                wmma::load_matrix_sync(bh[i], sBh + (wn + i * 16) * 40 + kk, 40);
                wmma::load_matrix_sync(bl[i], sBl + (wn + i * 16) * 40 + kk, 40);
            }
#pragma unroll
            for (int i = 0; i < 2; i++)
#pragma unroll
                for (int j = 0; j < 2; j++) {
                    wmma::mma_sync(acc[i][j], ah[i], bh[j], acc[i][j]);
                    wmma::mma_sync(acc[i][j], ah[i], bl[j], acc[i][j]);
                    wmma::mma_sync(acc[i][j], al[i], bh[j], acc[i][j]);
                }
        }
    }
    __syncthreads();
#pragma unroll
    for (int i = 0; i < 2; i++)
#pragma unroll
        for (int j = 0; j < 2; j++)
            wmma::store_matrix_sync(Cs + (wm + i * 16) * 68 + wn + j * 16, acc[i][j], 68,
                                    wmma::mem_row_major);
    __syncthreads();

    // epilogue: 128 rows x 16 units (i,f,g,o adjacent)
    const int ucol0 = col0 >> 2;
    for (int idx = tid; idx < 128 * 16; idx += 256) {
        int r  = idx >> 4, ul = idx & 15;
        int b  = row0 + r;
        int ug = ucol0 + ul;
        const float4 xg = *(const float4*)(XG + ((size_t)b * NT + t) * N + 4 * ug);
        float ip = Cs[r * 68 + ul * 4 + 0] + xg.x;
        float fp = Cs[r * 68 + ul * 4 + 1] + xg.y;
        float gp = Cs[r * 68 + ul * 4 + 2] + xg.z;
        float op = Cs[r * 68 + ul * 4 + 3] + xg.w;
        size_t ci = (size_t)b * H + ug;
        float c = sigmf(fp) * C[ci] + sigmf(ip) * tanh_f(gp);
        float h = sigmf(op) * tanh_f(c);
        C[ci] = c;
        bsplit(h, Hnh[ci], Hnl[ci]);
        size_t so = ((size_t)b * NT + t) * H + ug;
        bsplit(fmaxf(h, 0.f), Sh[so], Sl[so]);
    }
}

// t=0 cell (h0=c0=0)
__global__ void gate_init(const float* __restrict__ XG, float* __restrict__ C,
                          bf16* __restrict__ Hh, bf16* __restrict__ Hl,
                          bf16* __restrict__ Sh, bf16* __restrict__ Sl, int H) {
    int i = blockIdx.x * blockDim.x + threadIdx.x;
    if (i >= NB2 * H) return;
    int b = i / H, u = i - b * H;
    const float4 xg = *(const float4*)(XG + (size_t)b * NT * (4 * H) + 4 * u);
    float c = sigmf(xg.x) * tanh_f(xg.z);
    float h = sigmf(xg.w) * tanh_f(c);
    C[i] = c;
    bsplit(h, Hh[i], Hl[i]);
    size_t so = (size_t)b * NT * H + u;
    bsplit(fmaxf(h, 0.f), Sh[so], Sl[so]);
}

__global__ void absdiff(const bf16* __restrict__ S3h, const bf16* __restrict__ S3l,
                        bf16* __restrict__ Dh, bf16* __restrict__ Dl) {
    size_t i = (size_t)blockIdx.x * blockDim.x + threadIdx.x;
    if (i >= (size_t)NB * 1920) return;
    size_t j = i + (size_t)NB * 1920;
    float h1 = __bfloat162float(S3h[i]) + __bfloat162float(S3l[i]);
    float h2 = __bfloat162float(S3h[j]) + __bfloat162float(S3l[j]);
    bsplit(fabsf(h1 - h2), Dh[i], Dl[i]);
}

// fused FC3(480->16, relu) + FC4(16->1)
__global__ void fc34(const float* __restrict__ F2, const float* __restrict__ Wf3,
                     const float* __restrict__ bf3, const float* __restrict__ Wf4,
                     const float* __restrict__ bf4, float* __restrict__ out) {
    __shared__ float row[480];
    __shared__ float acc16[16];
    int b = blockIdx.x, tid = threadIdx.x;
    for (int i = tid; i < 480; i += 256) row[i] = F2[(size_t)b * 480 + i];
    __syncthreads();
    int n = tid >> 4, lane = tid & 15;
    float s = 0.f;
    for (int k = lane; k < 480; k += 16) s += row[k] * Wf3[n * 480 + k];
#pragma unroll
    for (int off = 8; off; off >>= 1) s += __shfl_down_sync(0xffffffffu, s, off, 16);
    if (lane == 0) acc16[n] = fmaxf(s + bf3[n], 0.f) * Wf4[n];
    __syncthreads();
    if (tid == 0) {
        float r = bf4[0];
#pragma unroll
        for (int i = 0; i < 16; i++) r += acc16[i];
        out[b] = r;
    }
}

// ---------------- host orchestration ----------------
extern "C" void kernel_launch(void* const* d_in, const int* in_sizes, int n_in,
                              void* d_out, int out_size) {
    (void)in_sizes; (void)out_size;
    if (n_in < 19) return;
    const float* x1   = (const float*)d_in[0];
    const float* x2   = (const float*)d_in[1];
    const float* Wih1 = (const float*)d_in[2];
    const float* Whh1 = (const float*)d_in[3];
    const float* b1   = (const float*)d_in[4];
    const float* Wih2 = (const float*)d_in[5];
    const float* Whh2 = (const float*)d_in[6];
    const float* b2   = (const float*)d_in[7];
    const float* Wih3 = (const float*)d_in[8];
    const float* Whh3 = (const float*)d_in[9];
    const float* b3   = (const float*)d_in[10];
    const float* Wf1  = (const float*)d_in[11];
    const float* bf1  = (const float*)d_in[12];
    const float* Wf2  = (const float*)d_in[13];
    const float* bf2  = (const float*)d_in[14];
    const float* Wf3  = (const float*)d_in[15];
    const float* bf3  = (const float*)d_in[16];
    const float* Wf4  = (const float*)d_in[17];
    const float* bf4  = (const float*)d_in[18];

    bf16 *Xh,*Xl,*S1h,*S1l,*S2h,*S2l,*S3h,*S3l,*Hah,*Hal,*Hbh,*Hbl,*Dh,*Dl,*F1h,*F1l;
    bf16 *W1ihh,*W1ihl,*W1hhh,*W1hhl,*W2ihh,*W2ihl,*W2hhh,*W2hhl,*W3ihh,*W3ihl,*W3hhh,*W3hhl;
    bf16 *Wf1h,*Wf1l,*Wf2h,*Wf2l;
    float *XG1,*XG2,*XG3,*Cc,*F2,*b1p,*b2p,*b3p;
    cudaGetSymbolAddress((void**)&Xh, g_Xh);     cudaGetSymbolAddress((void**)&Xl, g_Xl);
    cudaGetSymbolAddress((void**)&XG1, g_XG1);
    cudaGetSymbolAddress((void**)&S1h, g_S1h);   cudaGetSymbolAddress((void**)&S1l, g_S1l);
    cudaGetSymbolAddress((void**)&XG2, g_XG2);
    cudaGetSymbolAddress((void**)&S2h, g_S2h);   cudaGetSymbolAddress((void**)&S2l, g_S2l);
    cudaGetSymbolAddress((void**)&XG3, g_XG3);
    cudaGetSymbolAddress((void**)&S3h, g_S3h);   cudaGetSymbolAddress((void**)&S3l, g_S3l);
    cudaGetSymbolAddress((void**)&Hah, g_Hah);   cudaGetSymbolAddress((void**)&Hal, g_Hal);
    cudaGetSymbolAddress((void**)&Hbh, g_Hbh);   cudaGetSymbolAddress((void**)&Hbl, g_Hbl);
    cudaGetSymbolAddress((void**)&Cc, g_Cc);
    cudaGetSymbolAddress((void**)&Dh, g_Dh);     cudaGetSymbolAddress((void**)&Dl, g_Dl);
    cudaGetSymbolAddress((void**)&F1h, g_F1h);   cudaGetSymbolAddress((void**)&F1l, g_F1l);
    cudaGetSymbolAddress((void**)&F2, g_F2);
    cudaGetSymbolAddress((void**)&W1ihh, g_W1ih_h); cudaGetSymbolAddress((void**)&W1ihl, g_W1ih_l);
    cudaGetSymbolAddress((void**)&W1hhh, g_W1hh_h); cudaGetSymbolAddress((void**)&W1hhl, g_W1hh_l);
    cudaGetSymbolAddress((void**)&W2ihh, g_W2ih_h); cudaGetSymbolAddress((void**)&W2ihl, g_W2ih_l);
    cudaGetSymbolAddress((void**)&W2hhh, g_W2hh_h); cudaGetSymbolAddress((void**)&W2hhl, g_W2hh_l);
    cudaGetSymbolAddress((void**)&W3ihh, g_W3ih_h); cudaGetSymbolAddress((void**)&W3ihl, g_W3ih_l);
    cudaGetSymbolAddress((void**)&W3hhh, g_W3hh_h); cudaGetSymbolAddress((void**)&W3hhl, g_W3hh_l);
    cudaGetSymbolAddress((void**)&b1p, g_b1p);
    cudaGetSymbolAddress((void**)&b2p, g_b2p);
    cudaGetSymbolAddress((void**)&b3p, g_b3p);
    cudaGetSymbolAddress((void**)&Wf1h, g_Wf1h); cudaGetSymbolAddress((void**)&Wf1l, g_Wf1l);
    cudaGetSymbolAddress((void**)&Wf2h, g_Wf2h); cudaGetSymbolAddress((void**)&Wf2l, g_Wf2l);

    // prep
    pack_x<<<61440, 256>>>(x1, x2, Xh, Xl);
    perm_wih1_s<<<512, 256>>>(Wih1, W1ihh, W1ihl);
    perm_w_s<<<4096, 256>>>(Whh1, W1hhh, W1hhl, 512, 512);
    perm_b<<<8, 256>>>(b1, b1p, 512);
    perm_w_s<<<1024, 256>>>(Wih2, W2ihh, W2ihl, 128, 512);
    perm_w_s<<<256, 256>>>(Whh2, W2hhh, W2hhl, 128, 128);
    perm_b<<<2, 256>>>(b2, b2p, 128);
    perm_w_s<<<128, 256>>>(Wih3, W3ihh, W3ihl, 64, 128);
    perm_w_s<<<64, 256>>>(Whh3, W3hhh, W3hhl, 64, 64);
    perm_b<<<1, 256>>>(b3, b3p, 64);
    split_mat<<<7200, 256>>>(Wf1, Wf1h, Wf1l, (size_t)960 * 1920);
    split_mat<<<1800, 256>>>(Wf2, Wf2h, Wf2l, (size_t)480 * 960);

    const int MBT = NB2 * NT;  // 245760

    // ---- layer 1: 58(->64) -> 512 ----
    gemm_bs<<<dim3(32, MBT / 128), 256>>>(Xh, Xl, W1ihh, W1ihl, b1p,
                                          XG1, nullptr, nullptr, MBT, 2048, 64, 0);
    gate_init<<<(NB2 * 512) / 256, 256>>>(XG1, Cc, Hah, Hal, S1h, S1l, 512);
    for (int t = 1; t < NT; t++) {
        bf16* ih = (t & 1) ? Hah : Hbh;  bf16* il = (t & 1) ? Hal : Hbl;
        bf16* oh = (t & 1) ? Hbh : Hah;  bf16* ol = (t & 1) ? Hbl : Hal;
        lstm_step<<<dim3(32, NB2 / 128), 256>>>(ih, il, W1hhh, W1hhl, XG1, Cc,
                                                oh, ol, S1h, S1l, 512, t);
    }

    // ---- layer 2: 512 -> 128 ----
    gemm_bs<<<dim3(8, MBT / 128), 256>>>(S1h, S1l, W2ihh, W2ihl, b2p,
                                         XG2, nullptr, nullptr, MBT, 512, 512, 0);
    gate_init<<<(NB2 * 128) / 256, 256>>>(XG2, Cc, Hah, Hal, S2h, S2l, 128);
    for (int t = 1; t < NT; t++) {
        bf16* ih = (t & 1) ? Hah : Hbh;  bf16* il = (t & 1) ? Hal : Hbl;
        bf16* oh = (t & 1) ? Hbh : Hah;  bf16* ol = (t & 1) ? Hbl : Hal;
        lstm_step<<<dim3(8, NB2 / 128), 256>>>(ih, il, W2hhh, W2hhl, XG2, Cc,
                                               oh, ol, S2h, S2l, 128, t);
    }

    // ---- layer 3: 128 -> 64 ----
    gemm_bs<<<dim3(4, MBT / 128), 256>>>(S2h, S2l, W3ihh, W3ihl, b3p,
                                         XG3, nullptr, nullptr, MBT, 256, 128, 0);
    gate_init<<<(NB2 * 64) / 256, 256>>>(XG3, Cc, Hah, Hal, S3h, S3l, 64);
    for (int t = 1; t < NT; t++) {
        bf16* ih = (t & 1) ? Hah : Hbh;  bf16* il = (t & 1) ? Hal : Hbl;
        bf16* oh = (t & 1) ? Hbh : Hah;  bf16* ol = (t & 1) ? Hbl : Hal;
        lstm_step<<<dim3(4, NB2 / 128), 256>>>(ih, il, W3hhh, W3hhl, XG3, Cc,
                                               oh, ol, S3h, S3l, 64, t);
    }

    // ---- siamese diff + FC head ----
    absdiff<<<(NB * 1920) / 256, 256>>>(S3h, S3l, Dh, Dl);
    gemm_bs<<<dim3(15, NB / 128), 256>>>(Dh, Dl, Wf1h, Wf1l, bf1,
                                         nullptr, F1h, F1l, NB, 960, 1920, 1);
    gemm_bs<<<dim3(8, NB / 128), 256>>>(F1h, F1l, Wf2h, Wf2l, bf2,
                                        F2, nullptr, nullptr, NB, 480, 960, 1);
    fc34<<<NB, 256>>>(F2, Wf3, bf3, Wf4, bf4, (float*)d_out);
}